// round 14
// baseline (speedup 1.0000x reference)
#include <cuda_runtime.h>
#include <cuda_bf16.h>
#include <cstdint>

#define NN 8192
#define FOUT 256

// per-stage: PH(5120) PL(5120) WH(36864 = 256n x 144B) = 47104 B, 4 stages
#define STG_SZ 47104u
#define PL_D   5120u
#define WH_D   10240u
#define MB_OFF 188416u           // 4 x (full,empty) pairs, 16B apart
#define ZS_OFF 188480u
#define SM_TOT 188800u

// ---------------- scratch globals ----------------
__device__ float g_Wh[NN * FOUT];                                  // 8 MB
__device__ __align__(16) __nv_bfloat16 g_WhTi[256 * 256 * 64];     // [jtile][n][hi32|lo32]
__device__ float g_E1[NN], g_B1[NN], g_E2[NN], g_F2[NN];

__device__ __forceinline__ uint32_t s2u(const void* p) {
    uint32_t a;
    asm("{ .reg .u64 t; cvta.to.shared.u64 t, %1; cvt.u32.u64 %0, t; }" : "=r"(a) : "l"(p));
    return a;
}
__device__ __forceinline__ void mma16816(float* d, const uint32_t* a,
                                         uint32_t b0, uint32_t b1) {
    asm volatile(
        "mma.sync.aligned.m16n8k16.row.col.f32.bf16.bf16.f32 "
        "{%0,%1,%2,%3}, {%4,%5,%6,%7}, {%8,%9}, {%0,%1,%2,%3};"
        : "+f"(d[0]), "+f"(d[1]), "+f"(d[2]), "+f"(d[3])
        : "r"(a[0]), "r"(a[1]), "r"(a[2]), "r"(a[3]), "r"(b0), "r"(b1));
}
__device__ __forceinline__ void ldsm4(uint32_t* r, uint32_t addr) {
    asm volatile("ldmatrix.sync.aligned.m8n8.x4.shared.b16 {%0,%1,%2,%3}, [%4];"
                 : "=r"(r[0]), "=r"(r[1]), "=r"(r[2]), "=r"(r[3]) : "r"(addr));
}
__device__ __forceinline__ void mbar_wait(uint32_t mb, uint32_t par) {
    asm volatile(
        "{\n\t.reg .pred P1;\n\tW%=:\n\t"
        "mbarrier.try_wait.parity.acquire.cta.shared::cta.b64 P1, [%0], %1, 0x989680;\n\t"
        "@P1 bra.uni D%=;\n\tbra.uni W%=;\n\tD%=:\n\t}"
        :: "r"(mb), "r"(par) : "memory");
}
__device__ __forceinline__ void mbar_arrive(uint32_t mb) {
    asm volatile("mbarrier.arrive.shared.b64 _, [%0];" :: "r"(mb) : "memory");
}

// ---------------------------------------------------------------------------
// K1: Wh = h @ W, fused with transposed hi/lo tile build (k_tr absorbed).
// 512 blocks x 256 thr, 16 rows/block; block covers half of one 32-row j-tile.
// ---------------------------------------------------------------------------
__global__ void __launch_bounds__(256) k_wh(const float* __restrict__ h,
                                            const float* __restrict__ W) {
    __shared__ float Ws[32][256];
    __shared__ float hs[16][32];
    int t = threadIdx.x, r0 = blockIdx.x * 16;
    float acc[16];
#pragma unroll
    for (int r = 0; r < 16; r++) acc[r] = 0.f;
    for (int kc = 0; kc < 8; kc++) {
        __syncthreads();
#pragma unroll
        for (int kk = 0; kk < 32; kk++) Ws[kk][t] = W[(kc * 32 + kk) * FOUT + t];
        {
            int r = t >> 4, c2 = (t & 15) * 2;
            float2 v = *(const float2*)&h[(r0 + r) * FOUT + kc * 32 + c2];
            hs[r][c2] = v.x; hs[r][c2 + 1] = v.y;
        }
        __syncthreads();
#pragma unroll
        for (int kk = 0; kk < 32; kk++) {
            float w = Ws[kk][t];
#pragma unroll
            for (int r = 0; r < 16; r++) acc[r] = fmaf(hs[r][kk], w, acc[r]);
        }
    }
#pragma unroll
    for (int r = 0; r < 16; r++) g_Wh[(r0 + r) * FOUT + t] = acc[r];

    // transposed hi/lo pack: rows r0..r0+15 are half of j-tile kb
    int kb = r0 >> 5, half = (r0 >> 4) & 1;
    uint32_t hi16[8], lo16[8];
#pragma unroll
    for (int rp = 0; rp < 8; rp++) {
        float v0 = acc[2 * rp], v1 = acc[2 * rp + 1];
        __nv_bfloat16 h0 = __float2bfloat16(v0), h1 = __float2bfloat16(v1);
        float l0 = v0 - __bfloat162float(h0), l1 = v1 - __bfloat162float(h1);
        __nv_bfloat16 g0 = __float2bfloat16(l0), g1 = __float2bfloat16(l1);
        hi16[rp] = (uint32_t)__bfloat16_as_ushort(h1) << 16 | __bfloat16_as_ushort(h0);
        lo16[rp] = (uint32_t)__bfloat16_as_ushort(g1) << 16 | __bfloat16_as_ushort(g0);
    }
    __nv_bfloat16* dst = &g_WhTi[((size_t)kb * 256 + t) * 64 + half * 16];
    *(uint4*)(dst)          = make_uint4(hi16[0], hi16[1], hi16[2], hi16[3]);
    *(uint4*)(dst + 8)      = make_uint4(hi16[4], hi16[5], hi16[6], hi16[7]);
    *(uint4*)(dst + 32)     = make_uint4(lo16[0], lo16[1], lo16[2], lo16[3]);
    *(uint4*)(dst + 40)     = make_uint4(lo16[4], lo16[5], lo16[6], lo16[7]);
}

// ---------------------------------------------------------------------------
// K1b: exp factors. exp(lrelu(s1+s2)) = max(E1*E2, B1*F2).
// ---------------------------------------------------------------------------
__global__ void __launch_bounds__(256) k_s12(const float* __restrict__ a) {
    int warp = threadIdx.x >> 5, lane = threadIdx.x & 31;
    int r = blockIdx.x * 8 + warp;
    const float4* wh = (const float4*)&g_Wh[r * FOUT];
    float v1 = 0.f, v2 = 0.f;
#pragma unroll
    for (int i = 0; i < 2; i++) {
        int k4 = lane + i * 32;
        float4 w  = wh[k4];
        float4 a1 = *(const float4*)&a[k4 * 4];
        float4 a2 = *(const float4*)&a[FOUT + k4 * 4];
        v1 += w.x * a1.x + w.y * a1.y + w.z * a1.z + w.w * a1.w;
        v2 += w.x * a2.x + w.y * a2.y + w.z * a2.z + w.w * a2.w;
    }
#pragma unroll
    for (int o = 16; o; o >>= 1) {
        v1 += __shfl_down_sync(~0u, v1, o);
        v2 += __shfl_down_sync(~0u, v2, o);
    }
    if (lane == 0) {
        g_E1[r] = __expf(v1);  g_B1[r] = __expf(0.2f * v1);
        g_E2[r] = __expf(v2);  g_F2[r] = __expf(0.2f * v2);
    }
}

// ---------------------------------------------------------------------------
// K2: warp-specialized, full-width CTAs. 128 CTAs (M=64, N=256), 384 thr.
// Warps 0-3 produce (P gen + Wh cp.async + adj prefetch + Z).
// Warps 4-11 consume: warp tile M16 x N128 (cw>>1 -> m, cw&1 -> n half).
// 4-stage mbarrier ring; cp completion via cp.async.mbarrier.arrive.noinc.
// full count = 256 (128 gen + 128 cp); empty count = 256 (consumer threads).
// ---------------------------------------------------------------------------
__global__ void __launch_bounds__(384, 1) k_attn(const int* __restrict__ adj,
                                                 float* __restrict__ out) {
    extern __shared__ char sm[];
    uint32_t sb = s2u(sm);
    uint32_t mbF = sb + MB_OFF;        // full[s] at +s*16, empty[s] at +s*16+8

    int t = threadIdx.x, w = t >> 5, lane = t & 31;
    int r0 = blockIdx.x * 64;

    if (t == 0) {
#pragma unroll
        for (int s = 0; s < 4; s++) {
            asm volatile("mbarrier.init.shared.b64 [%0], 256;" :: "r"(mbF + s * 16) : "memory");
            asm volatile("mbarrier.init.shared.b64 [%0], 256;" :: "r"(mbF + s * 16 + 8) : "memory");
        }
    }
    __syncthreads();

    if (w < 4) {
        // ================= PRODUCER (128 threads) =================
        int kp = t & 15, rsub = t >> 4;          // rsub 0..7
        uint32_t whDst = sb + WH_D + (uint32_t)(t * 144);
        const char* cpSrc = (const char*)&g_WhTi[(size_t)t * 64];

        float e1r[8], b1r[8], zacc[8];
#pragma unroll
        for (int it = 0; it < 8; it++) {
            int r = it * 8 + rsub;
            e1r[it] = g_E1[r0 + r];
            b1r[it] = g_B1[r0 + r];
            zacc[it] = 0.f;
        }
        int2 adjv[8];
#pragma unroll
        for (int it = 0; it < 8; it++)
            adjv[it] = *(const int2*)&adj[(long long)(r0 + it * 8 + rsub) * NN + 2 * kp];

        int s = 0; uint32_t kpar = 0;
        for (int i = 0; i < 256; i++) {
            mbar_wait(mbF + s * 16 + 8, 1u ^ kpar);      // empty[s]
            uint32_t stg = s * STG_SZ;
            // Wh tile: rows t and t+128 (128B each from packed WhTi)
            {
                const char* src = cpSrc + (size_t)i * 32768;
                uint32_t d = whDst + stg;
#pragma unroll
                for (int s4 = 0; s4 < 8; s4++)
                    asm volatile("cp.async.cg.shared.global [%0], [%1], 16;"
                                 :: "r"(d + s4 * 16), "l"(src + s4 * 16) : "memory");
                src += 128 * 64 * 2;   // row t+128
                d += 128 * 144;
#pragma unroll
                for (int s4 = 0; s4 < 8; s4++)
                    asm volatile("cp.async.cg.shared.global [%0], [%1], 16;"
                                 :: "r"(d + s4 * 16), "l"(src + s4 * 16) : "memory");
                asm volatile("cp.async.mbarrier.arrive.noinc.shared.b64 [%0];"
                             :: "r"(mbF + s * 16) : "memory");
            }
            // P gen into stage s
            {
                char* phb = sm + stg;
                char* plb = sm + stg + PL_D;
                float2 e2 = *(const float2*)&g_E2[i * 32 + 2 * kp];
                float2 f2 = *(const float2*)&g_F2[i * 32 + 2 * kp];
#pragma unroll
                for (int it = 0; it < 8; it++) {
                    int r = it * 8 + rsub;
                    float p0 = adjv[it].x ? fmaxf(e1r[it] * e2.x, b1r[it] * f2.x) : 0.f;
                    float p1 = adjv[it].y ? fmaxf(e1r[it] * e2.y, b1r[it] * f2.y) : 0.f;
                    zacc[it] += p0 + p1;
                    uint32_t hp;
                    asm("cvt.rn.bf16x2.f32 %0, %1, %2;" : "=r"(hp) : "f"(p1), "f"(p0));
                    float h0f = __uint_as_float(hp << 16);
                    float h1f = __uint_as_float(hp & 0xffff0000u);
                    uint32_t lp;
                    asm("cvt.rn.bf16x2.f32 %0, %1, %2;" : "=r"(lp) : "f"(p1 - h1f), "f"(p0 - h0f));
                    *(uint32_t*)(phb + r * 80 + kp * 4) = hp;
                    *(uint32_t*)(plb + r * 80 + kp * 4) = lp;
                }
            }
            if (i < 255) {
#pragma unroll
                for (int it = 0; it < 8; it++)
                    adjv[it] = *(const int2*)&adj[(long long)(r0 + it * 8 + rsub) * NN
                                                 + (i + 1) * 32 + 2 * kp];
            }
            mbar_arrive(mbF + s * 16);                   // full[s] (gen part)
            if (++s == 4) { s = 0; kpar ^= 1u; }
        }

        float* Zs = (float*)(sm + ZS_OFF);
#pragma unroll
        for (int it = 0; it < 8; it++) {
            float z = zacc[it];
            z += __shfl_xor_sync(~0u, z, 1);
            z += __shfl_xor_sync(~0u, z, 2);
            z += __shfl_xor_sync(~0u, z, 4);
            z += __shfl_xor_sync(~0u, z, 8);
            if ((lane & 15) == 0) Zs[it * 8 + rsub] = z;
        }
    } else {
        // ================= CONSUMER (warps 4-11) =================
        int cw = w - 4;
        int mb = (cw >> 1) * 16;                 // 0,16,32,48
        int nb = (cw & 1) * 128;                 // n half
        uint32_t aBase = sb + (uint32_t)((mb + (lane & 15)) * 80 + (lane >> 4) * 16);
        uint32_t bBase = sb + WH_D +
            (uint32_t)((nb + (lane >> 4) * 8 + (lane & 7)) * 144 + ((lane >> 3) & 1) * 16);

        float acc[16][4];
#pragma unroll
        for (int nt = 0; nt < 16; nt++)
#pragma unroll
            for (int e = 0; e < 4; e++) acc[nt][e] = 0.f;

        int s = 0; uint32_t kpar = 0;
        for (int i = 0; i < 256; i++) {
            mbar_wait(mbF + s * 16, kpar);               // full[s]
            uint32_t stg = s * STG_SZ;
            uint32_t aH = aBase + stg, aL = aH + PL_D, bB = bBase + stg;
#pragma unroll
            for (int ks = 0; ks < 2; ks++) {
                uint32_t Ah[4], Al[4];
                ldsm4(Ah, aH + ks * 32);
                ldsm4(Al, aL + ks * 32);
#pragma unroll
                for (int npp = 0; npp < 4; npp++) {
                    uint32_t Bh0[4], Bh1[4], Bl0[4], Bl1[4];
                    uint32_t bb0 = bB + (2 * npp) * 2304 + ks * 32;
                    uint32_t bb1 = bb0 + 2304;
                    ldsm4(Bh0, bb0); ldsm4(Bh1, bb1);
                    ldsm4(Bl0, bb0 + 64); ldsm4(Bl1, bb1 + 64);
                    int a0 = 4 * npp;
                    mma16816(acc[a0],     Ah, Bh0[0], Bh0[1]);
                    mma16816(acc[a0 + 1], Ah, Bh0[2], Bh0[3]);
                    mma16816(acc[a0 + 2], Ah, Bh1[0], Bh1[1]);
                    mma16816(acc[a0 + 3], Ah, Bh1[2], Bh1[3]);
                    mma16816(acc[a0],     Al, Bh0[0], Bh0[1]);
                    mma16816(acc[a0 + 1], Al, Bh0[2], Bh0[3]);
                    mma16816(acc[a0 + 2], Al, Bh1[0], Bh1[1]);
                    mma16816(acc[a0 + 3], Al, Bh1[2], Bh1[3]);
                    mma16816(acc[a0],     Ah, Bl0[0], Bl0[1]);
                    mma16816(acc[a0 + 1], Ah, Bl0[2], Bl0[3]);
                    mma16816(acc[a0 + 2], Ah, Bl1[0], Bl1[1]);
                    mma16816(acc[a0 + 3], Ah, Bl1[2], Bl1[3]);
                }
            }
            mbar_arrive(mbF + s * 16 + 8);               // empty[s]
            if (++s == 4) { s = 0; kpar ^= 1u; }
        }

        __syncthreads();   // join: Zs ready  [A]
        float* Zs = (float*)(sm + ZS_OFF);
        int g = lane >> 2, quad = lane & 3;
        int rl = mb + g;
        float zi0 = __frcp_rn(Zs[rl]);
        float zi1 = __frcp_rn(Zs[rl + 8]);
#pragma unroll
        for (int nt = 0; nt < 16; nt++) {
            int c = nb + nt * 8 + quad * 2;
            *(float2*)&out[(size_t)(r0 + rl) * FOUT + c] =
                make_float2(acc[nt][0] * zi0, acc[nt][1] * zi0);
            *(float2*)&out[(size_t)(r0 + rl + 8) * FOUT + c] =
                make_float2(acc[nt][2] * zi1, acc[nt][3] * zi1);
        }
        return;
    }
    __syncthreads();       // producers join [A]
}

// ---------------------------------------------------------------------------
extern "C" void kernel_launch(void* const* d_in, const int* in_sizes, int n_in,
                              void* d_out, int out_size) {
    const float* h   = (const float*)d_in[0];
    const int*   adj = (const int*)d_in[1];
    const float* W   = (const float*)d_in[2];
    const float* a   = (const float*)d_in[3];
    float* out = (float*)d_out;

    cudaFuncSetAttribute(k_attn, cudaFuncAttributeMaxDynamicSharedMemorySize, SM_TOT);

    k_wh<<<512, 256>>>(h, W);
    k_s12<<<1024, 256>>>(a);
    k_attn<<<128, 384, SM_TOT>>>(adj, out);
}

// round 15
// speedup vs baseline: 1.4193x; 1.4193x over previous
#include <cuda_runtime.h>
#include <cuda_bf16.h>
#include <cstdint>

#define NN 8192
#define FOUT 256

// per-stage layout: PH(5120) PL(5120) WH(18432) = 28672 B, 3 stages
#define STG_SZ 28672u
#define PL_D   5120u
#define WH_D   10240u
#define MB_OFF 86016u            // (full,empty) x3, 16B apart
#define ZS_OFF 86144u
#define SM_TOT 86400u

// ---------------- scratch globals ----------------
__device__ float g_Wh[NN * FOUT];                                  // 8 MB
__device__ __align__(16) __nv_bfloat16 g_WhTi[256 * 256 * 64];     // [jtile][n][hi32|lo32]
__device__ float g_E1[NN], g_B1[NN], g_E2[NN], g_F2[NN];

__device__ __forceinline__ uint32_t s2u(const void* p) {
    uint32_t a;
    asm("{ .reg .u64 t; cvta.to.shared.u64 t, %1; cvt.u32.u64 %0, t; }" : "=r"(a) : "l"(p));
    return a;
}
__device__ __forceinline__ void mma16816(float* d, const uint32_t* a,
                                         uint32_t b0, uint32_t b1) {
    asm volatile(
        "mma.sync.aligned.m16n8k16.row.col.f32.bf16.bf16.f32 "
        "{%0,%1,%2,%3}, {%4,%5,%6,%7}, {%8,%9}, {%0,%1,%2,%3};"
        : "+f"(d[0]), "+f"(d[1]), "+f"(d[2]), "+f"(d[3])
        : "r"(a[0]), "r"(a[1]), "r"(a[2]), "r"(a[3]), "r"(b0), "r"(b1));
}
__device__ __forceinline__ void ldsm4(uint32_t* r, uint32_t addr) {
    asm volatile("ldmatrix.sync.aligned.m8n8.x4.shared.b16 {%0,%1,%2,%3}, [%4];"
                 : "=r"(r[0]), "=r"(r[1]), "=r"(r[2]), "=r"(r[3]) : "r"(addr));
}
__device__ __forceinline__ void mbar_wait(uint32_t mb, uint32_t par) {
    asm volatile(
        "{\n\t.reg .pred P1;\n\tW%=:\n\t"
        "mbarrier.try_wait.parity.acquire.cta.shared::cta.b64 P1, [%0], %1, 0x989680;\n\t"
        "@P1 bra.uni D%=;\n\tbra.uni W%=;\n\tD%=:\n\t}"
        :: "r"(mb), "r"(par) : "memory");
}
__device__ __forceinline__ void mbar_arrive(uint32_t mb) {
    asm volatile("mbarrier.arrive.shared.b64 _, [%0];" :: "r"(mb) : "memory");
}

// ---------------------------------------------------------------------------
// K1: Wh = h @ W
// ---------------------------------------------------------------------------
__global__ void __launch_bounds__(256) k_wh(const float* __restrict__ h,
                                            const float* __restrict__ W) {
    __shared__ float Ws[32][256];
    __shared__ float hs[16][32];
    int t = threadIdx.x, r0 = blockIdx.x * 16;
    float acc[16];
#pragma unroll
    for (int r = 0; r < 16; r++) acc[r] = 0.f;
    for (int kc = 0; kc < 8; kc++) {
        __syncthreads();
#pragma unroll
        for (int kk = 0; kk < 32; kk++) Ws[kk][t] = W[(kc * 32 + kk) * FOUT + t];
        {
            int r = t >> 4, c2 = (t & 15) * 2;
            float2 v = *(const float2*)&h[(r0 + r) * FOUT + kc * 32 + c2];
            hs[r][c2] = v.x; hs[r][c2 + 1] = v.y;
        }
        __syncthreads();
#pragma unroll
        for (int kk = 0; kk < 32; kk++) {
            float w = Ws[kk][t];
#pragma unroll
            for (int r = 0; r < 16; r++) acc[r] = fmaf(hs[r][kk], w, acc[r]);
        }
    }
#pragma unroll
    for (int r = 0; r < 16; r++) g_Wh[(r0 + r) * FOUT + t] = acc[r];
}

// ---------------------------------------------------------------------------
// K1t: WhTi[kb][n][64] = [hi bf16 of Wh[kb*32+r][n] r=0..31 | lo ...]
// ---------------------------------------------------------------------------
__global__ void __launch_bounds__(256) k_tr() {
    int t = threadIdx.x, kb = blockIdx.x;
    float v[32];
#pragma unroll
    for (int r = 0; r < 32; r++) v[r] = g_Wh[(kb * 32 + r) * FOUT + t];
    uint32_t hi16[16], lo16[16];
#pragma unroll
    for (int rp = 0; rp < 16; rp++) {
        float v0 = v[2 * rp], v1 = v[2 * rp + 1];
        __nv_bfloat16 h0 = __float2bfloat16(v0), h1 = __float2bfloat16(v1);
        float l0 = v0 - __bfloat162float(h0), l1 = v1 - __bfloat162float(h1);
        __nv_bfloat16 g0 = __float2bfloat16(l0), g1 = __float2bfloat16(l1);
        hi16[rp] = (uint32_t)__bfloat16_as_ushort(h1) << 16 | __bfloat16_as_ushort(h0);
        lo16[rp] = (uint32_t)__bfloat16_as_ushort(g1) << 16 | __bfloat16_as_ushort(g0);
    }
    __nv_bfloat16* dst = &g_WhTi[((size_t)kb * 256 + t) * 64];
#pragma unroll
    for (int s = 0; s < 4; s++) {
        *(uint4*)(dst + s * 8)      = make_uint4(hi16[4*s], hi16[4*s+1], hi16[4*s+2], hi16[4*s+3]);
        *(uint4*)(dst + 32 + s * 8) = make_uint4(lo16[4*s], lo16[4*s+1], lo16[4*s+2], lo16[4*s+3]);
    }
}

// ---------------------------------------------------------------------------
// K1b: exp factors
// ---------------------------------------------------------------------------
__global__ void __launch_bounds__(256) k_s12(const float* __restrict__ a) {
    int warp = threadIdx.x >> 5, lane = threadIdx.x & 31;
    int r = blockIdx.x * 8 + warp;
    const float4* wh = (const float4*)&g_Wh[r * FOUT];
    float v1 = 0.f, v2 = 0.f;
#pragma unroll
    for (int i = 0; i < 2; i++) {
        int k4 = lane + i * 32;
        float4 w  = wh[k4];
        float4 a1 = *(const float4*)&a[k4 * 4];
        float4 a2 = *(const float4*)&a[FOUT + k4 * 4];
        v1 += w.x * a1.x + w.y * a1.y + w.z * a1.z + w.w * a1.w;
        v2 += w.x * a2.x + w.y * a2.y + w.z * a2.z + w.w * a2.w;
    }
#pragma unroll
    for (int o = 16; o; o >>= 1) {
        v1 += __shfl_down_sync(~0u, v1, o);
        v2 += __shfl_down_sync(~0u, v2, o);
    }
    if (lane == 0) {
        g_E1[r] = __expf(v1);  g_B1[r] = __expf(0.2f * v1);
        g_E2[r] = __expf(v2);  g_F2[r] = __expf(0.2f * v2);
    }
}

// ---------------------------------------------------------------------------
// K2: warp-specialized producer/consumer + HMMA, 512 threads.
// 256 CTAs = 128 rb (M=64) x 2 cb (N=128). Warps 0-7 produce, 8-15 consume.
// Consumer warp tile M16 x N64. 3-stage mbarrier ring, 2 CTAs/SM.
// ---------------------------------------------------------------------------
__global__ void __launch_bounds__(512, 2) k_attn(const int* __restrict__ adj,
                                                 float* __restrict__ out) {
    extern __shared__ char sm[];
    uint32_t sb = s2u(sm);
    uint32_t mbF = sb + MB_OFF;        // full[s] at +s*16, empty[s] at +s*16+8

    int t = threadIdx.x, w = t >> 5, lane = t & 31;
    int rb = blockIdx.x >> 1, cb = blockIdx.x & 1;
    int r0 = rb * 64;

    if (t == 0) {
#pragma unroll
        for (int s = 0; s < 3; s++) {
            asm volatile("mbarrier.init.shared.b64 [%0], 256;" :: "r"(mbF + s * 16) : "memory");
            asm volatile("mbarrier.init.shared.b64 [%0], 256;" :: "r"(mbF + s * 16 + 8) : "memory");
        }
    }
    __syncthreads();

    if (w < 8) {
        // ================= PRODUCER (256 threads) =================
        int kp = t & 15, rsub = t >> 4;            // rsub 0..15 -> 4 rows each
        uint32_t whDst = sb + WH_D + (uint32_t)((t >> 1) * 144 + (t & 1) * 64);
        const char* cpSrc =
            (const char*)&g_WhTi[((size_t)cb * 128 + (t >> 1)) * 64 + (t & 1) * 32];

        float e1r[4], b1r[4], zacc[4];
#pragma unroll
        for (int it = 0; it < 4; it++) {
            int r = it * 16 + rsub;
            e1r[it] = g_E1[r0 + r];
            b1r[it] = g_B1[r0 + r];
            zacc[it] = 0.f;
        }
        int2 adjv[4];
#pragma unroll
        for (int it = 0; it < 4; it++)
            adjv[it] = *(const int2*)&adj[(long long)(r0 + it * 16 + rsub) * NN + 2 * kp];

        int s = 0; uint32_t kpar = 0;
        for (int i = 0; i < 256; i++) {
            mbar_wait(mbF + s * 16 + 8, 1u ^ kpar);      // empty[s]
            uint32_t stg = s * STG_SZ;
            // Wh tile: 64B per thread from pre-split WhTi
            {
                const char* src = cpSrc + (size_t)i * 32768;
                uint32_t d = whDst + stg;
#pragma unroll
                for (int s4 = 0; s4 < 4; s4++)
                    asm volatile("cp.async.cg.shared.global [%0], [%1], 16;"
                                 :: "r"(d + s4 * 16), "l"(src + s4 * 16) : "memory");
                asm volatile("cp.async.commit_group;" ::: "memory");
            }
            // P gen into stage s (4 rows)
            {
                char* phb = sm + stg;
                char* plb = sm + stg + PL_D;
                float2 e2 = *(const float2*)&g_E2[i * 32 + 2 * kp];
                float2 f2 = *(const float2*)&g_F2[i * 32 + 2 * kp];
#pragma unroll
                for (int it = 0; it < 4; it++) {
                    int r = it * 16 + rsub;
                    float p0 = adjv[it].x ? fmaxf(e1r[it] * e2.x, b1r[it] * f2.x) : 0.f;
                    float p1 = adjv[it].y ? fmaxf(e1r[it] * e2.y, b1r[it] * f2.y) : 0.f;
                    zacc[it] += p0 + p1;
                    uint32_t hp;
                    asm("cvt.rn.bf16x2.f32 %0, %1, %2;" : "=r"(hp) : "f"(p1), "f"(p0));
                    float h0f = __uint_as_float(hp << 16);
                    float h1f = __uint_as_float(hp & 0xffff0000u);
                    uint32_t lp;
                    asm("cvt.rn.bf16x2.f32 %0, %1, %2;" : "=r"(lp) : "f"(p1 - h1f), "f"(p0 - h0f));
                    *(uint32_t*)(phb + r * 80 + kp * 4) = hp;
                    *(uint32_t*)(plb + r * 80 + kp * 4) = lp;
                }
            }
            if (i < 255) {
#pragma unroll
                for (int it = 0; it < 4; it++)
                    adjv[it] = *(const int2*)&adj[(long long)(r0 + it * 16 + rsub) * NN
                                                 + (i + 1) * 32 + 2 * kp];
            }
            asm volatile("cp.async.wait_group 0;" ::: "memory");
            mbar_arrive(mbF + s * 16);                   // full[s]
            if (++s == 3) { s = 0; kpar ^= 1u; }
        }

        float* Zs = (float*)(sm + ZS_OFF);
#pragma unroll
        for (int it = 0; it < 4; it++) {
            float z = zacc[it];
            z += __shfl_xor_sync(~0u, z, 1);
            z += __shfl_xor_sync(~0u, z, 2);
            z += __shfl_xor_sync(~0u, z, 4);
            z += __shfl_xor_sync(~0u, z, 8);
            if ((lane & 15) == 0) Zs[it * 16 + rsub] = z;
        }
    } else {
        // ================= CONSUMER (warps 8-15) =================
        int cw = w - 8;
        int mb = (cw >> 1) * 16;                 // 0,16,32,48
        int nb = (cw & 1) * 64;                  // n half within N=128
        uint32_t aBase = sb + (uint32_t)((mb + (lane & 15)) * 80 + (lane >> 4) * 16);
        uint32_t bBase = sb + WH_D +
            (uint32_t)((nb + (lane >> 4) * 8 + (lane & 7)) * 144 + ((lane >> 3) & 1) * 16);

        float acc[8][4];
#pragma unroll
        for (int nt = 0; nt < 8; nt++)
#pragma unroll
            for (int e = 0; e < 4; e++) acc[nt][e] = 0.f;

        int s = 0; uint32_t kpar = 0;
        for (int i = 0; i < 256; i++) {
            mbar_wait(mbF + s * 16, kpar);               // full[s]
            uint32_t stg = s * STG_SZ;
            uint32_t aH = aBase + stg, aL = aH + PL_D, bB = bBase + stg;
#pragma unroll
            for (int ks = 0; ks < 2; ks++) {
                uint32_t Ah[4], Al[4];
                ldsm4(Ah, aH + ks * 32);
                ldsm4(Al, aL + ks * 32);
#pragma unroll
                for (int npp = 0; npp < 2; npp++) {
                    uint32_t Bh0[4], Bh1[4], Bl0[4], Bl1[4];
                    uint32_t bb0 = bB + (2 * npp) * 2304 + ks * 32;
                    uint32_t bb1 = bb0 + 2304;
                    ldsm4(Bh0, bb0); ldsm4(Bh1, bb1);
                    ldsm4(Bl0, bb0 + 64); ldsm4(Bl1, bb1 + 64);
                    int a0 = 4 * npp;
                    mma16816(acc[a0],     Ah, Bh0[0], Bh0[1]);
                    mma16816(acc[a0 + 1], Ah, Bh0[2], Bh0[3]);
                    mma16816(acc[a0 + 2], Ah, Bh1[0], Bh1[1]);
                    mma16816(acc[a0 + 3], Ah, Bh1[2], Bh1[3]);
                    mma16816(acc[a0],     Al, Bh0[0], Bh0[1]);
                    mma16816(acc[a0 + 1], Al, Bh0[2], Bh0[3]);
                    mma16816(acc[a0 + 2], Al, Bh1[0], Bh1[1]);
                    mma16816(acc[a0 + 3], Al, Bh1[2], Bh1[3]);
                    mma16816(acc[a0],     Ah, Bl0[0], Bl0[1]);
                    mma16816(acc[a0 + 1], Ah, Bl0[2], Bl0[3]);
                    mma16816(acc[a0 + 2], Ah, Bl1[0], Bl1[1]);
                    mma16816(acc[a0 + 3], Ah, Bl1[2], Bl1[3]);
                }
            }
            mbar_arrive(mbF + s * 16 + 8);               // empty[s]
            if (++s == 3) { s = 0; kpar ^= 1u; }
        }

        __syncthreads();   // join with producers (Zs ready)  [A]
        float* Zs = (float*)(sm + ZS_OFF);
        int g = lane >> 2, quad = lane & 3;
        int rl = mb + g;
        float zi0 = __frcp_rn(Zs[rl]);
        float zi1 = __frcp_rn(Zs[rl + 8]);
#pragma unroll
        for (int nt = 0; nt < 8; nt++) {
            int c = cb * 128 + nb + nt * 8 + quad * 2;
            *(float2*)&out[(size_t)(r0 + rl) * FOUT + c] =
                make_float2(acc[nt][0] * zi0, acc[nt][1] * zi0);
            *(float2*)&out[(size_t)(r0 + rl + 8) * FOUT + c] =
                make_float2(acc[nt][2] * zi1, acc[nt][3] * zi1);
        }
        return;
    }
    __syncthreads();       // producers join [A]
}

// ---------------------------------------------------------------------------
extern "C" void kernel_launch(void* const* d_in, const int* in_sizes, int n_in,
                              void* d_out, int out_size) {
    const float* h   = (const float*)d_in[0];
    const int*   adj = (const int*)d_in[1];
    const float* W   = (const float*)d_in[2];
    const float* a   = (const float*)d_in[3];
    float* out = (float*)d_out;

    cudaFuncSetAttribute(k_attn, cudaFuncAttributeMaxDynamicSharedMemorySize, SM_TOT);

    k_wh<<<512, 256>>>(h, W);
    k_tr<<<256, 256>>>();
    k_s12<<<1024, 256>>>(a);
    k_attn<<<256, 512, SM_TOT>>>(adj, out);
}

// round 17
// speedup vs baseline: 1.6747x; 1.1799x over previous
#include <cuda_runtime.h>
#include <cuda_fp16.h>
#include <cstdint>

#define NN 8192
#define FOUT 256

// per-stage: PH(5120 = 64r x 80B) PL(5120) WH(10240 = 128n x 80B) = 20480, 4 stages
#define STG_SZ 20480u
#define PL_D   5120u
#define WH_D   10240u
#define MB_OFF 81920u            // (full,empty) x4, 16B apart
#define ZS_OFF 81984u
#define SM_TOT 82432u

// ---------------- scratch globals ----------------
__device__ float g_Wh[NN * FOUT];                              // 8 MB
__device__ __align__(16) __half g_WhTi[256 * 256 * 32];        // [jtile][n][32 fp16]
__device__ float g_E1[NN], g_B1[NN], g_E2[NN], g_F2[NN];

__device__ __forceinline__ uint32_t s2u(const void* p) {
    uint32_t a;
    asm("{ .reg .u64 t; cvta.to.shared.u64 t, %1; cvt.u32.u64 %0, t; }" : "=r"(a) : "l"(p));
    return a;
}
__device__ __forceinline__ void mma16816(float* d, const uint32_t* a,
                                         uint32_t b0, uint32_t b1) {
    asm volatile(
        "mma.sync.aligned.m16n8k16.row.col.f32.f16.f16.f32 "
        "{%0,%1,%2,%3}, {%4,%5,%6,%7}, {%8,%9}, {%0,%1,%2,%3};"
        : "+f"(d[0]), "+f"(d[1]), "+f"(d[2]), "+f"(d[3])
        : "r"(a[0]), "r"(a[1]), "r"(a[2]), "r"(a[3]), "r"(b0), "r"(b1));
}
__device__ __forceinline__ void ldsm4(uint32_t* r, uint32_t addr) {
    asm volatile("ldmatrix.sync.aligned.m8n8.x4.shared.b16 {%0,%1,%2,%3}, [%4];"
                 : "=r"(r[0]), "=r"(r[1]), "=r"(r[2]), "=r"(r[3]) : "r"(addr));
}
__device__ __forceinline__ void mbar_wait(uint32_t mb, uint32_t par) {
    asm volatile(
        "{\n\t.reg .pred P1;\n\tW%=:\n\t"
        "mbarrier.try_wait.parity.acquire.cta.shared::cta.b64 P1, [%0], %1, 0x989680;\n\t"
        "@P1 bra.uni D%=;\n\tbra.uni W%=;\n\tD%=:\n\t}"
        :: "r"(mb), "r"(par) : "memory");
}
__device__ __forceinline__ void mbar_arrive(uint32_t mb) {
    asm volatile("mbarrier.arrive.shared.b64 _, [%0];" :: "r"(mb) : "memory");
}

// ---------------------------------------------------------------------------
// K1: Wh = h @ W
// ---------------------------------------------------------------------------
__global__ void __launch_bounds__(256) k_wh(const float* __restrict__ h,
                                            const float* __restrict__ W) {
    __shared__ float Ws[32][256];
    __shared__ float hs[16][32];
    int t = threadIdx.x, r0 = blockIdx.x * 16;
    float acc[16];
#pragma unroll
    for (int r = 0; r < 16; r++) acc[r] = 0.f;
    for (int kc = 0; kc < 8; kc++) {
        __syncthreads();
#pragma unroll
        for (int kk = 0; kk < 32; kk++) Ws[kk][t] = W[(kc * 32 + kk) * FOUT + t];
        {
            int r = t >> 4, c2 = (t & 15) * 2;
            float2 v = *(const float2*)&h[(r0 + r) * FOUT + kc * 32 + c2];
            hs[r][c2] = v.x; hs[r][c2 + 1] = v.y;
        }
        __syncthreads();
#pragma unroll
        for (int kk = 0; kk < 32; kk++) {
            float w = Ws[kk][t];
#pragma unroll
            for (int r = 0; r < 16; r++) acc[r] = fmaf(hs[r][kk], w, acc[r]);
        }
    }
#pragma unroll
    for (int r = 0; r < 16; r++) g_Wh[(r0 + r) * FOUT + t] = acc[r];
}

// ---------------------------------------------------------------------------
// K1t: WhTi[kb][n][32] = fp16(Wh[kb*32+r][n]), r ascending (k-major fragment)
// ---------------------------------------------------------------------------
__global__ void __launch_bounds__(256) k_tr() {
    int t = threadIdx.x, kb = blockIdx.x;
    float v[32];
#pragma unroll
    for (int r = 0; r < 32; r++) v[r] = g_Wh[(kb * 32 + r) * FOUT + t];
    uint32_t pk[16];
#pragma unroll
    for (int rp = 0; rp < 16; rp++) {
        __half2 hh = __floats2half2_rn(v[2 * rp], v[2 * rp + 1]);
        pk[rp] = *(uint32_t*)&hh;
    }
    __half* dst = &g_WhTi[((size_t)kb * 256 + t) * 32];
#pragma unroll
    for (int s = 0; s < 4; s++)
        *(uint4*)(dst + s * 8) = make_uint4(pk[4*s], pk[4*s+1], pk[4*s+2], pk[4*s+3]);
}

// ---------------------------------------------------------------------------
// K1b: exp factors. exp(lrelu(s1+s2)) = max(E1*E2, B1*F2).
// ---------------------------------------------------------------------------
__global__ void __launch_bounds__(256) k_s12(const float* __restrict__ a) {
    int warp = threadIdx.x >> 5, lane = threadIdx.x & 31;
    int r = blockIdx.x * 8 + warp;
    const float4* wh = (const float4*)&g_Wh[r * FOUT];
    float v1 = 0.f, v2 = 0.f;
#pragma unroll
    for (int i = 0; i < 2; i++) {
        int k4 = lane + i * 32;
        float4 w  = wh[k4];
        float4 a1 = *(const float4*)&a[k4 * 4];
        float4 a2 = *(const float4*)&a[FOUT + k4 * 4];
        v1 += w.x * a1.x + w.y * a1.y + w.z * a1.z + w.w * a1.w;
        v2 += w.x * a2.x + w.y * a2.y + w.z * a2.z + w.w * a2.w;
    }
#pragma unroll
    for (int o = 16; o; o >>= 1) {
        v1 += __shfl_down_sync(~0u, v1, o);
        v2 += __shfl_down_sync(~0u, v2, o);
    }
    if (lane == 0) {
        g_E1[r] = __expf(v1);  g_B1[r] = __expf(0.2f * v1);
        g_E2[r] = __expf(v2);  g_F2[r] = __expf(0.2f * v2);
    }
}

// ---------------------------------------------------------------------------
// K2: warp-specialized producer/consumer, fp16 2-term split.
// 256 CTAs = 128 rb (M=64) x 2 cb (N=128). 512 thr: warps 0-7 produce,
// 8-15 consume (warp tile M16 x N64). 4-stage mbarrier ring, 2 CTAs/SM.
// D = Ph*Whh + Pl*Whh  (Whh = fp16(Wh); err ~2^-11, < 1e-3 threshold)
// ---------------------------------------------------------------------------
__global__ void __launch_bounds__(512, 2) k_attn(const int* __restrict__ adj,
                                                 float* __restrict__ out) {
    extern __shared__ char sm[];
    uint32_t sb = s2u(sm);
    uint32_t mbF = sb + MB_OFF;        // full[s] +s*16, empty[s] +s*16+8

    int t = threadIdx.x, w = t >> 5, lane = t & 31;
    int rb = blockIdx.x >> 1, cb = blockIdx.x & 1;
    int r0 = rb * 64;

    if (t == 0) {
#pragma unroll
        for (int s = 0; s < 4; s++) {
            asm volatile("mbarrier.init.shared.b64 [%0], 256;" :: "r"(mbF + s * 16) : "memory");
            asm volatile("mbarrier.init.shared.b64 [%0], 256;" :: "r"(mbF + s * 16 + 8) : "memory");
        }
    }
    __syncthreads();

    if (w < 8) {
        // ================= PRODUCER (256 threads) =================
        int kp = t & 15, rsub = t >> 4;            // 4 rows each
        uint32_t whDst = sb + WH_D + (uint32_t)((t >> 1) * 80 + (t & 1) * 32);
        const char* cpSrc =
            (const char*)&g_WhTi[((size_t)cb * 128 + (t >> 1)) * 32 + (t & 1) * 16];

        float e1r[4], b1r[4], zacc[4];
#pragma unroll
        for (int it = 0; it < 4; it++) {
            int r = it * 16 + rsub;
            e1r[it] = g_E1[r0 + r];
            b1r[it] = g_B1[r0 + r];
            zacc[it] = 0.f;
        }
        int2 adjv[4];
#pragma unroll
        for (int it = 0; it < 4; it++)
            adjv[it] = *(const int2*)&adj[(long long)(r0 + it * 16 + rsub) * NN + 2 * kp];

        int s = 0; uint32_t kpar = 0;
        for (int i = 0; i < 256; i++) {
            mbar_wait(mbF + s * 16 + 8, 1u ^ kpar);      // empty[s]
            uint32_t stg = s * STG_SZ;
            // Wh tile: 32B per thread (fp16, hi only)
            {
                const char* src = cpSrc + (size_t)i * 16384;   // 256n * 32 fp16 * 2B
                uint32_t d = whDst + stg;
                asm volatile("cp.async.cg.shared.global [%0], [%1], 16;"
                             :: "r"(d), "l"(src) : "memory");
                asm volatile("cp.async.cg.shared.global [%0], [%1], 16;"
                             :: "r"(d + 16), "l"(src + 16) : "memory");
                asm volatile("cp.async.commit_group;" ::: "memory");
            }
            // P gen (fp16 hi + residual lo)
            {
                char* phb = sm + stg;
                char* plb = sm + stg + PL_D;
                float2 e2 = *(const float2*)&g_E2[i * 32 + 2 * kp];
                float2 f2 = *(const float2*)&g_F2[i * 32 + 2 * kp];
#pragma unroll
                for (int it = 0; it < 4; it++) {
                    int r = it * 16 + rsub;
                    float p0 = adjv[it].x ? fmaxf(e1r[it] * e2.x, b1r[it] * f2.x) : 0.f;
                    float p1 = adjv[it].y ? fmaxf(e1r[it] * e2.y, b1r[it] * f2.y) : 0.f;
                    zacc[it] += p0 + p1;
                    __half2 hh = __floats2half2_rn(p0, p1);
                    float2 hf = __half22float2(hh);
                    __half2 ll = __floats2half2_rn(p0 - hf.x, p1 - hf.y);
                    *(uint32_t*)(phb + r * 80 + kp * 4) = *(uint32_t*)&hh;
                    *(uint32_t*)(plb + r * 80 + kp * 4) = *(uint32_t*)&ll;
                }
            }
            if (i < 255) {
#pragma unroll
                for (int it = 0; it < 4; it++)
                    adjv[it] = *(const int2*)&adj[(long long)(r0 + it * 16 + rsub) * NN
                                                 + (i + 1) * 32 + 2 * kp];
            }
            asm volatile("cp.async.wait_group 0;" ::: "memory");
            mbar_arrive(mbF + s * 16);                   // full[s]
            if (++s == 4) { s = 0; kpar ^= 1u; }
        }

        float* Zs = (float*)(sm + ZS_OFF);
#pragma unroll
        for (int it = 0; it < 4; it++) {
            float z = zacc[it];
            z += __shfl_xor_sync(~0u, z, 1);
            z += __shfl_xor_sync(~0u, z, 2);
            z += __shfl_xor_sync(~0u, z, 4);
            z += __shfl_xor_sync(~0u, z, 8);
            if ((lane & 15) == 0) Zs[it * 16 + rsub] = z;
        }
    } else {
        // ================= CONSUMER (warps 8-15) =================
        int cw = w - 8;
        int mb = (cw >> 1) * 16;                 // 0,16,32,48
        int nb = (cw & 1) * 64;                  // n half within N=128
        uint32_t aBase = sb + (uint32_t)((mb + (lane & 15)) * 80 + (lane >> 4) * 16);
        uint32_t bBase = sb + WH_D +
            (uint32_t)((nb + (lane >> 4) * 8 + (lane & 7)) * 80 + ((lane >> 3) & 1) * 16);

        float acc[8][4];
#pragma unroll
        for (int nt = 0; nt < 8; nt++)
#pragma unroll
            for (int e = 0; e < 4; e++) acc[nt][e] = 0.f;

        int s = 0; uint32_t kpar = 0;
        for (int i = 0; i < 256; i++) {
            mbar_wait(mbF + s * 16, kpar);               // full[s]
            uint32_t stg = s * STG_SZ;
            uint32_t aH = aBase + stg, aL = aH + PL_D, bB = bBase + stg;
#pragma unroll
            for (int ks = 0; ks < 2; ks++) {
                uint32_t Ah[4], Al[4];
                ldsm4(Ah, aH + ks * 32);
                ldsm4(Al, aL + ks * 32);
#pragma unroll
                for (int npp = 0; npp < 2; npp++) {
                    uint32_t Bh0[4], Bh1[4];
                    uint32_t bb0 = bB + (2 * npp) * 1280 + ks * 32;   // 16n x 80B
                    ldsm4(Bh0, bb0);
                    ldsm4(Bh1, bb0 + 1280);
                    int a0 = 4 * npp;
                    mma16816(acc[a0],     Ah, Bh0[0], Bh0[1]);
                    mma16816(acc[a0 + 1], Ah, Bh0[2], Bh0[3]);
                    mma16816(acc[a0 + 2], Ah, Bh1[0], Bh1[1]);
                    mma16816(acc[a0 + 3], Ah, Bh1[2], Bh1[3]);
                    mma16816(acc[a0],     Al, Bh0[0], Bh0[1]);
                    mma16816(acc[a0 + 1], Al, Bh0[2], Bh0[3]);
                    mma16816(acc[a0 + 2], Al, Bh1[0], Bh1[1]);
                    mma16816(acc[a0 + 3], Al, Bh1[2], Bh1[3]);
                }
            }
            mbar_arrive(mbF + s * 16 + 8);               // empty[s]
            if (++s == 4) { s = 0; kpar ^= 1u; }
        }

        __syncthreads();   // join with producers (Zs ready)  [A]
        float* Zs = (float*)(sm + ZS_OFF);
        int g = lane >> 2, quad = lane & 3;
        int rl = mb + g;
        float zi0 = __frcp_rn(Zs[rl]);
        float zi1 = __frcp_rn(Zs[rl + 8]);
#pragma unroll
        for (int nt = 0; nt < 8; nt++) {
            int c = cb * 128 + nb + nt * 8 + quad * 2;
            *(float2*)&out[(size_t)(r0 + rl) * FOUT + c] =
                make_float2(acc[nt][0] * zi0, acc[nt][1] * zi0);
            *(float2*)&out[(size_t)(r0 + rl + 8) * FOUT + c] =
                make_float2(acc[nt][2] * zi1, acc[nt][3] * zi1);
        }
        return;
    }
    __syncthreads();       // producers join [A]
}

// ---------------------------------------------------------------------------
extern "C" void kernel_launch(void* const* d_in, const int* in_sizes, int n_in,
                              void* d_out, int out_size) {
    const float* h   = (const float*)d_in[0];
    const int*   adj = (const int*)d_in[1];
    const float* W   = (const float*)d_in[2];
    const float* a   = (const float*)d_in[3];
    float* out = (float*)d_out;

    cudaFuncSetAttribute(k_attn, cudaFuncAttributeMaxDynamicSharedMemorySize, SM_TOT);

    k_wh<<<512, 256>>>(h, W);
    k_tr<<<256, 256>>>();
    k_s12<<<1024, 256>>>(a);
    k_attn<<<256, 512, SM_TOT>>>(adj, out);
}